// round 2
// baseline (speedup 1.0000x reference)
#include <cuda_runtime.h>

#define NN  100000
#define NE  1600000
#define NEL 6400000
#define EPSV 1e-5

// ---------------- scratch (device globals; no allocation allowed) ----------
__device__ float  g_yx[(size_t)NN * 16];
__device__ float  g_x1[(size_t)NN * 16];
__device__ float  g_x2[(size_t)NN * 16];
__device__ float  g_x4[(size_t)NN * 16];
__device__ float  g_xt[(size_t)NN * 16];
__device__ float  g_xy[(size_t)NE * 16];   // xy gather; later reused as A^3 y temp
__device__ float  g_ya[(size_t)NE * 16];   // xy_agg
__device__ float  g_y1[(size_t)NE * 16];
__device__ float  g_y2[(size_t)NE * 16];
__device__ float  g_y4[(size_t)NE * 16];
__device__ double g_stats[64];             // [0:16) sum, [16:32) sumsq (x); +32 for y
__device__ float  g_coef[64];              // scale/shift for BN (x: 0..31, y: 32..63)

// ---------------- kernels --------------------------------------------------

// out[dst[e]] += z[src[e]]   (4 threads per edge, float4 vector reductions)
__global__ void __launch_bounds__(256) k_spmm(
    const float* __restrict__ z, const int* __restrict__ src,
    const int* __restrict__ dst, float* __restrict__ out, int nE)
{
    long t = (long)blockIdx.x * 256 + threadIdx.x;
    int e = (int)(t >> 2);
    if (e >= nE) return;
    int c = (int)(t & 3);
    int s = __ldg(src + e);
    int d = __ldg(dst + e);
    float4 v = __ldg(reinterpret_cast<const float4*>(z) + ((size_t)s << 2) + c);
    atomicAdd(reinterpret_cast<float4*>(out) + (((size_t)d << 2) + c), v);
}

// out[dst[e]] += z[e]
__global__ void __launch_bounds__(256) k_scatter(
    const float* __restrict__ z, const int* __restrict__ dst,
    float* __restrict__ out, int nE)
{
    long t = (long)blockIdx.x * 256 + threadIdx.x;
    int e = (int)(t >> 2);
    if (e >= nE) return;
    int c = (int)(t & 3);
    int d = __ldg(dst + e);
    float4 v = __ldg(reinterpret_cast<const float4*>(z) + ((size_t)e << 2) + c);
    atomicAdd(reinterpret_cast<float4*>(out) + (((size_t)d << 2) + c), v);
}

// out[e] = x[idx[e]]
__global__ void __launch_bounds__(256) k_gather(
    const float* __restrict__ x, const int* __restrict__ idx,
    float* __restrict__ out, int nE)
{
    long t = (long)blockIdx.x * 256 + threadIdx.x;
    int e = (int)(t >> 2);
    if (e >= nE) return;
    int c = (int)(t & 3);
    int s = __ldg(idx + e);
    reinterpret_cast<float4*>(out)[((size_t)e << 2) + c] =
        __ldg(reinterpret_cast<const float4*>(x) + ((size_t)s << 2) + c);
}

// h = xn[:, :16] + relu(xn[:, 16:]) where
// xn = z0@W0' + (deg*z0)@W1' + t2@W2' + t3@W3' + t4@W4' + t5@W5' + sum(b)
// Also accumulates BN stats (sum, sumsq per channel) into stats[0:32].
__global__ void __launch_bounds__(256) k_combine(
    const float* __restrict__ z0, const float* __restrict__ deg,
    const float* __restrict__ t2p, const float* __restrict__ t3p,
    const float* __restrict__ t4p, const float* __restrict__ t5p,
    const float* __restrict__ W, const float* __restrict__ B,
    float* __restrict__ out, double* __restrict__ stats, int n)
{
    __shared__ float4 sW[768];     // 6 * 32 * 16 floats
    __shared__ float  sB[32];
    __shared__ float  sRed[32];
    int tid = threadIdx.x;
    const float4* W4 = reinterpret_cast<const float4*>(W);
    for (int i = tid; i < 768; i += 256) sW[i] = W4[i];
    if (tid < 32) {
        float b = 0.f;
        #pragma unroll
        for (int t = 0; t < 6; t++) b += B[t * 32 + tid];
        sB[tid] = b;
        sRed[tid] = 0.f;
    }
    __syncthreads();

    long r = (long)blockIdx.x * 256 + tid;
    bool act = (r < (long)n);
    float h[16];
    if (act) {
        float acc[32];
        #pragma unroll
        for (int j = 0; j < 32; j++) acc[j] = sB[j];
        float dg = __ldg(deg + r);
        #pragma unroll
        for (int t = 0; t < 6; t++) {
            const float* zp = (t <= 1) ? z0 : (t == 2 ? t2p : (t == 3 ? t3p : (t == 4 ? t4p : t5p)));
            const float4* z4p = reinterpret_cast<const float4*>(zp) + ((size_t)r << 2);
            float4 a0 = __ldg(z4p + 0);
            float4 a1 = __ldg(z4p + 1);
            float4 a2 = __ldg(z4p + 2);
            float4 a3 = __ldg(z4p + 3);
            if (t == 1) {
                a0.x *= dg; a0.y *= dg; a0.z *= dg; a0.w *= dg;
                a1.x *= dg; a1.y *= dg; a1.z *= dg; a1.w *= dg;
                a2.x *= dg; a2.y *= dg; a2.z *= dg; a2.w *= dg;
                a3.x *= dg; a3.y *= dg; a3.z *= dg; a3.w *= dg;
            }
            #pragma unroll
            for (int j = 0; j < 32; j++) {
                const float4* w = &sW[(t * 32 + j) * 4];
                float4 w0 = w[0], w1 = w[1], w2 = w[2], w3 = w[3];
                float s = acc[j];
                s += a0.x * w0.x + a0.y * w0.y + a0.z * w0.z + a0.w * w0.w;
                s += a1.x * w1.x + a1.y * w1.y + a1.z * w1.z + a1.w * w1.w;
                s += a2.x * w2.x + a2.y * w2.y + a2.z * w2.z + a2.w * w2.w;
                s += a3.x * w3.x + a3.y * w3.y + a3.z * w3.z + a3.w * w3.w;
                acc[j] = s;
            }
        }
        #pragma unroll
        for (int j = 0; j < 16; j++) h[j] = acc[j] + fmaxf(acc[j + 16], 0.f);
        float4* o = reinterpret_cast<float4*>(out) + ((size_t)r << 2);
        o[0] = make_float4(h[0], h[1], h[2], h[3]);
        o[1] = make_float4(h[4], h[5], h[6], h[7]);
        o[2] = make_float4(h[8], h[9], h[10], h[11]);
        o[3] = make_float4(h[12], h[13], h[14], h[15]);
        #pragma unroll
        for (int c = 0; c < 16; c++) {
            atomicAdd(&sRed[c], h[c]);
            atomicAdd(&sRed[16 + c], h[c] * h[c]);
        }
    }
    __syncthreads();
    if (tid < 32) atomicAdd(&stats[tid], (double)sRed[tid]);
}

// Turn (sum, sumsq) into per-channel scale/shift.
__global__ void k_bnprep(const double* __restrict__ stats, const float* __restrict__ w,
                         const float* __restrict__ b, float* __restrict__ coef, double n)
{
    int c = threadIdx.x;
    if (c >= 16) return;
    double m   = stats[c] / n;
    double var = stats[16 + c] / n - m * m;
    double s   = (double)w[c] / sqrt(var + (double)EPSV);
    coef[c]      = (float)s;
    coef[16 + c] = (float)((double)b[c] - m * s);
}

// In-place h = h*scale + shift (per channel)
__global__ void __launch_bounds__(256) k_bn(
    float* __restrict__ h, const float* __restrict__ coef, long n4)
{
    long t = (long)blockIdx.x * 256 + threadIdx.x;
    if (t >= n4) return;
    int c = (int)(t & 3);
    float4 sc = reinterpret_cast<const float4*>(coef)[c];
    float4 sh = reinterpret_cast<const float4*>(coef)[4 + c];
    float4 v = reinterpret_cast<float4*>(h)[t];
    v.x = v.x * sc.x + sh.x;
    v.y = v.y * sc.y + sh.y;
    v.z = v.z * sc.z + sh.z;
    v.w = v.w * sc.w + sh.w;
    reinterpret_cast<float4*>(h)[t] = v;
}

// ---------------- host -----------------------------------------------------

static inline int cdiv(long a, int b) { return (int)((a + (long)b - 1) / b); }

extern "C" void kernel_launch(void* const* d_in, const int* in_sizes, int n_in,
                              void* d_out, int out_size)
{
    const float* x      = (const float*)d_in[0];
    const float* y      = (const float*)d_in[1];
    const float* deg_g  = (const float*)d_in[2];
    const float* deg_lg = (const float*)d_in[3];
    const float* thW    = (const float*)d_in[4];
    const float* thB    = (const float*)d_in[5];
    const float* gmW    = (const float*)d_in[6];
    const float* gmB    = (const float*)d_in[7];
    const float* bnxw   = (const float*)d_in[8];
    const float* bnxb   = (const float*)d_in[9];
    const float* bnyw   = (const float*)d_in[10];
    const float* bnyb   = (const float*)d_in[11];
    const int* src_g    = (const int*)d_in[12];
    const int* dst_g    = (const int*)d_in[13];
    const int* src_lg   = (const int*)d_in[14];
    const int* dst_lg   = (const int*)d_in[15];
    const int* eid      = (const int*)d_in[16];

    int N  = in_sizes[2];   // deg_g count
    int E  = in_sizes[3];   // deg_lg count
    int EL = in_sizes[14];  // src_lg count

    float *p_yx, *p_x1, *p_x2, *p_x4, *p_xt, *p_xy, *p_ya, *p_y1, *p_y2, *p_y4, *p_coef;
    double* p_stats;
    cudaGetSymbolAddress((void**)&p_yx, g_yx);
    cudaGetSymbolAddress((void**)&p_x1, g_x1);
    cudaGetSymbolAddress((void**)&p_x2, g_x2);
    cudaGetSymbolAddress((void**)&p_x4, g_x4);
    cudaGetSymbolAddress((void**)&p_xt, g_xt);
    cudaGetSymbolAddress((void**)&p_xy, g_xy);
    cudaGetSymbolAddress((void**)&p_ya, g_ya);
    cudaGetSymbolAddress((void**)&p_y1, g_y1);
    cudaGetSymbolAddress((void**)&p_y2, g_y2);
    cudaGetSymbolAddress((void**)&p_y4, g_y4);
    cudaGetSymbolAddress((void**)&p_stats, g_stats);
    cudaGetSymbolAddress((void**)&p_coef, g_coef);

    float* ox = (float*)d_out;
    float* oy = ox + (size_t)N * 16;

    const int TB = 256;
    size_t nodeBytes = (size_t)N * 64;
    size_t edgeBytes = (size_t)E * 64;

    // zero accumulators + stats
    cudaMemsetAsync(p_yx, 0, nodeBytes);
    cudaMemsetAsync(p_x1, 0, nodeBytes);
    cudaMemsetAsync(p_x2, 0, nodeBytes);
    cudaMemsetAsync(p_x4, 0, nodeBytes);
    cudaMemsetAsync(p_xt, 0, nodeBytes);
    cudaMemsetAsync(p_stats, 0, 64 * sizeof(double));

    // ---- node branch ----
    k_scatter<<<cdiv((long)E * 4, TB), TB>>>(y, dst_g, p_yx, E);
    k_spmm<<<cdiv((long)E * 4, TB), TB>>>(x,    src_g, dst_g, p_x1, E);
    k_spmm<<<cdiv((long)E * 4, TB), TB>>>(p_x1, src_g, dst_g, p_x2, E);
    k_spmm<<<cdiv((long)E * 4, TB), TB>>>(p_x2, src_g, dst_g, p_xt, E);
    k_spmm<<<cdiv((long)E * 4, TB), TB>>>(p_xt, src_g, dst_g, p_x4, E);
    k_combine<<<cdiv(N, TB), TB>>>(x, deg_g, p_yx, p_x1, p_x2, p_x4, thW, thB, ox, p_stats, N);
    k_bnprep<<<1, 16>>>(p_stats, bnxw, bnxb, p_coef, (double)N);
    k_bn<<<cdiv((long)N * 4, TB), TB>>>(ox, p_coef, (long)N * 4);

    // ---- edge (line-graph) branch ----
    k_gather<<<cdiv((long)E * 4, TB), TB>>>(x, eid, p_xy, E);
    cudaMemsetAsync(p_ya, 0, edgeBytes);
    k_spmm<<<cdiv((long)EL * 4, TB), TB>>>(p_xy, src_lg, dst_lg, p_ya, EL);   // xy_agg
    cudaMemsetAsync(p_y1, 0, edgeBytes);
    k_spmm<<<cdiv((long)EL * 4, TB), TB>>>(y,    src_lg, dst_lg, p_y1, EL);   // A y
    cudaMemsetAsync(p_y2, 0, edgeBytes);
    k_spmm<<<cdiv((long)EL * 4, TB), TB>>>(p_y1, src_lg, dst_lg, p_y2, EL);   // A^2 y
    cudaMemsetAsync(p_xy, 0, edgeBytes);                                      // reuse as temp
    k_spmm<<<cdiv((long)EL * 4, TB), TB>>>(p_y2, src_lg, dst_lg, p_xy, EL);   // A^3 y
    cudaMemsetAsync(p_y4, 0, edgeBytes);
    k_spmm<<<cdiv((long)EL * 4, TB), TB>>>(p_xy, src_lg, dst_lg, p_y4, EL);   // A^4 y
    k_combine<<<cdiv(E, TB), TB>>>(y, deg_lg, p_ya, p_y1, p_y2, p_y4, gmW, gmB, oy, p_stats + 32, E);
    k_bnprep<<<1, 16>>>(p_stats + 32, bnyw, bnyb, p_coef + 32, (double)E);
    k_bn<<<cdiv((long)E * 4, TB), TB>>>(oy, p_coef + 32, (long)E * 4);
}

// round 5
// speedup vs baseline: 1.1820x; 1.1820x over previous
#include <cuda_runtime.h>

#define NN   100000
#define NE   1600000
#define NEL  6400000
#define EPSV 1e-5

#define RPAD(x) (((x) + 4095) & ~4095)
#define RP_G  RPAD(NN)
#define RP_LG RPAD(NE)

// ---------------- scratch (device globals; no allocation allowed) ----------
__device__ float  g_yx[(size_t)NN * 16];
__device__ float  g_x1[(size_t)NN * 16];
__device__ float  g_x2[(size_t)NN * 16];
__device__ float  g_x4[(size_t)NN * 16];
__device__ float  g_xt[(size_t)NN * 16];
__device__ float  g_ya[(size_t)NE * 16];
__device__ float  g_y1[(size_t)NE * 16];
__device__ float  g_y2[(size_t)NE * 16];
__device__ float  g_y4[(size_t)NE * 16];
__device__ float  g_t3[(size_t)NE * 16];
__device__ int    g_cnt_g[RP_G];
__device__ int    g_rowptr_g[RP_G + 1];
__device__ int2   g_slots_g[NE];          // {src, edge_id}
__device__ int    g_bsum_g[2048];
__device__ int    g_cnt_lg[RP_LG];
__device__ int    g_rowptr_lg[RP_LG + 1];
__device__ int    g_slots_lg[NEL];        // src only
__device__ int    g_bsum_lg[2048];
__device__ double g_stats[64];
__device__ float  g_coef[64];

// ---------------- CSR build kernels ---------------------------------------

__global__ void __launch_bounds__(256) k_hist(
    const int* __restrict__ dst, int* __restrict__ cnt, int nE)
{
    long t = (long)blockIdx.x * 256 + threadIdx.x;
    if (t >= nE) return;
    atomicAdd(&cnt[__ldg(dst + t)], 1);
}

__global__ void __launch_bounds__(256) k_scan1(
    const int* __restrict__ cnt, int* __restrict__ bsum)
{
    __shared__ int sh[256];
    int b = blockIdx.x, tid = threadIdx.x;
    const int4* c4 = reinterpret_cast<const int4*>(cnt);
    long base = (long)b * 1024 + (long)tid * 4;
    int s = 0;
    #pragma unroll
    for (int i = 0; i < 4; i++) {
        int4 v = __ldg(c4 + base + i);
        s += v.x + v.y + v.z + v.w;
    }
    sh[tid] = s; __syncthreads();
    for (int off = 128; off > 0; off >>= 1) {
        if (tid < off) sh[tid] += sh[tid + off];
        __syncthreads();
    }
    if (tid == 0) bsum[b] = sh[0];
}

__global__ void __launch_bounds__(1024) k_scan2(int* __restrict__ bsum, int nb)
{
    __shared__ int s[2048];
    int tid = threadIdx.x;
    s[tid]        = (tid        < nb) ? bsum[tid]        : 0;
    s[tid + 1024] = (tid + 1024 < nb) ? bsum[tid + 1024] : 0;
    int off = 1;
    for (int d = 1024; d > 0; d >>= 1) {
        __syncthreads();
        if (tid < d) {
            int ai = off * (2 * tid + 1) - 1;
            int bi = off * (2 * tid + 2) - 1;
            s[bi] += s[ai];
        }
        off <<= 1;
    }
    if (tid == 0) s[2047] = 0;
    for (int d = 1; d < 2048; d <<= 1) {
        off >>= 1;
        __syncthreads();
        if (tid < d) {
            int ai = off * (2 * tid + 1) - 1;
            int bi = off * (2 * tid + 2) - 1;
            int t = s[ai]; s[ai] = s[bi]; s[bi] += t;
        }
    }
    __syncthreads();
    if (tid        < nb) bsum[tid]        = s[tid];
    if (tid + 1024 < nb) bsum[tid + 1024] = s[tid + 1024];
}

__global__ void __launch_bounds__(256) k_scan3(
    const int* __restrict__ cnt, const int* __restrict__ bsum,
    int* __restrict__ rowptr, int RP)
{
    __shared__ int sh[256];
    int b = blockIdx.x, tid = threadIdx.x;
    const int4* c4 = reinterpret_cast<const int4*>(cnt);
    long base4 = (long)b * 1024 + (long)tid * 4;
    int vals[16];
    int tsum = 0;
    #pragma unroll
    for (int i = 0; i < 4; i++) {
        int4 v = __ldg(c4 + base4 + i);
        vals[i * 4 + 0] = v.x; vals[i * 4 + 1] = v.y;
        vals[i * 4 + 2] = v.z; vals[i * 4 + 3] = v.w;
        tsum += v.x + v.y + v.z + v.w;
    }
    sh[tid] = tsum; __syncthreads();
    for (int off = 1; off < 256; off <<= 1) {
        int t2 = (tid >= off) ? sh[tid - off] : 0;
        __syncthreads();
        sh[tid] += t2;
        __syncthreads();
    }
    int run = __ldg(bsum + b) + sh[tid] - tsum;
    long base = (long)b * 4096 + (long)tid * 16;
    #pragma unroll
    for (int i = 0; i < 16; i++) { rowptr[base + i] = run; run += vals[i]; }
    if (b == gridDim.x - 1 && tid == 255) rowptr[RP] = run;
}

__global__ void __launch_bounds__(256) k_fill_lg(
    const int* __restrict__ src, const int* __restrict__ dst,
    const int* __restrict__ rowptr, int* __restrict__ cnt,
    int* __restrict__ slots, int nE)
{
    long t = (long)blockIdx.x * 256 + threadIdx.x;
    if (t >= nE) return;
    int d = __ldg(dst + t);
    int p = __ldg(rowptr + d) + atomicAdd(&cnt[d], 1);
    slots[p] = __ldg(src + t);
}

__global__ void __launch_bounds__(256) k_fill_g(
    const int* __restrict__ src, const int* __restrict__ dst,
    const int* __restrict__ rowptr, int* __restrict__ cnt,
    int2* __restrict__ slots, int nE)
{
    long t = (long)blockIdx.x * 256 + threadIdx.x;
    if (t >= nE) return;
    int d = __ldg(dst + t);
    int p = __ldg(rowptr + d) + atomicAdd(&cnt[d], 1);
    slots[p] = make_int2(__ldg(src + t), (int)t);
}

// ---------------- SpMM (pull mode, CSR, no atomics) ------------------------

#define F4(p) reinterpret_cast<const float4*>(p)

__device__ __forceinline__ void acc4(float4& a, float4 v) {
    a.x += v.x; a.y += v.y; a.z += v.z; a.w += v.w;
}

// out[r] = sum_{e in row r} z[slots[e]]    (int slots)
__global__ void __launch_bounds__(256) k_spmm_csr(
    const float* __restrict__ z, const int* __restrict__ rowptr,
    const int* __restrict__ slots, float* __restrict__ out, int R)
{
    long t = (long)blockIdx.x * 256 + threadIdx.x;
    int r = (int)(t >> 2);
    if (r >= R) return;
    int c = (int)(t & 3);
    int e   = __ldg(rowptr + r);
    int end = __ldg(rowptr + r + 1);
    float4 acc = make_float4(0.f, 0.f, 0.f, 0.f);
    for (; e + 4 <= end; e += 4) {
        int s0 = __ldg(slots + e + 0), s1 = __ldg(slots + e + 1);
        int s2 = __ldg(slots + e + 2), s3 = __ldg(slots + e + 3);
        float4 v0 = __ldg(F4(z) + (((size_t)s0 << 2) + c));
        float4 v1 = __ldg(F4(z) + (((size_t)s1 << 2) + c));
        float4 v2 = __ldg(F4(z) + (((size_t)s2 << 2) + c));
        float4 v3 = __ldg(F4(z) + (((size_t)s3 << 2) + c));
        acc4(acc, v0); acc4(acc, v1); acc4(acc, v2); acc4(acc, v3);
    }
    for (; e < end; e++) {
        int s = __ldg(slots + e);
        acc4(acc, __ldg(F4(z) + (((size_t)s << 2) + c)));
    }
    reinterpret_cast<float4*>(out)[((size_t)r << 2) + c] = acc;
}

// out[r] = sum_{e in row r} z[slots[e].x]  (int2 slots; uses src half only)
__global__ void __launch_bounds__(256) k_spmm_csr2(
    const float* __restrict__ z, const int* __restrict__ rowptr,
    const int2* __restrict__ slots, float* __restrict__ out, int R)
{
    long t = (long)blockIdx.x * 256 + threadIdx.x;
    int r = (int)(t >> 2);
    if (r >= R) return;
    int c = (int)(t & 3);
    int e   = __ldg(rowptr + r);
    int end = __ldg(rowptr + r + 1);
    float4 acc = make_float4(0.f, 0.f, 0.f, 0.f);
    for (; e + 4 <= end; e += 4) {
        int s0 = __ldg(slots + e + 0).x, s1 = __ldg(slots + e + 1).x;
        int s2 = __ldg(slots + e + 2).x, s3 = __ldg(slots + e + 3).x;
        float4 v0 = __ldg(F4(z) + (((size_t)s0 << 2) + c));
        float4 v1 = __ldg(F4(z) + (((size_t)s1 << 2) + c));
        float4 v2 = __ldg(F4(z) + (((size_t)s2 << 2) + c));
        float4 v3 = __ldg(F4(z) + (((size_t)s3 << 2) + c));
        acc4(acc, v0); acc4(acc, v1); acc4(acc, v2); acc4(acc, v3);
    }
    for (; e < end; e++) {
        int s = __ldg(slots + e).x;
        acc4(acc, __ldg(F4(z) + (((size_t)s << 2) + c)));
    }
    reinterpret_cast<float4*>(out)[((size_t)r << 2) + c] = acc;
}

// node pass1: x1[r] = sum x[src], yx[r] = sum y[eid]   (shared CSR walk)
__global__ void __launch_bounds__(256) k_node_pass1(
    const float* __restrict__ x, const float* __restrict__ y,
    const int* __restrict__ rowptr, const int2* __restrict__ slots,
    float* __restrict__ outx1, float* __restrict__ outyx, int R)
{
    long t = (long)blockIdx.x * 256 + threadIdx.x;
    int r = (int)(t >> 2);
    if (r >= R) return;
    int c = (int)(t & 3);
    int e   = __ldg(rowptr + r);
    int end = __ldg(rowptr + r + 1);
    float4 ax = make_float4(0.f, 0.f, 0.f, 0.f);
    float4 ay = make_float4(0.f, 0.f, 0.f, 0.f);
    for (; e + 2 <= end; e += 2) {
        int2 s0 = __ldg(slots + e + 0);
        int2 s1 = __ldg(slots + e + 1);
        float4 vx0 = __ldg(F4(x) + (((size_t)s0.x << 2) + c));
        float4 vy0 = __ldg(F4(y) + (((size_t)s0.y << 2) + c));
        float4 vx1 = __ldg(F4(x) + (((size_t)s1.x << 2) + c));
        float4 vy1 = __ldg(F4(y) + (((size_t)s1.y << 2) + c));
        acc4(ax, vx0); acc4(ax, vx1);
        acc4(ay, vy0); acc4(ay, vy1);
    }
    for (; e < end; e++) {
        int2 s = __ldg(slots + e);
        acc4(ax, __ldg(F4(x) + (((size_t)s.x << 2) + c)));
        acc4(ay, __ldg(F4(y) + (((size_t)s.y << 2) + c)));
    }
    reinterpret_cast<float4*>(outx1)[((size_t)r << 2) + c] = ax;
    reinterpret_cast<float4*>(outyx)[((size_t)r << 2) + c] = ay;
}

// line pass1: y1[r] = sum y[s], ya[r] = sum x[eid2nid[s]]  (shared CSR walk)
__global__ void __launch_bounds__(256) k_line_pass1(
    const float* __restrict__ y, const float* __restrict__ x,
    const int* __restrict__ eid2nid,
    const int* __restrict__ rowptr, const int* __restrict__ slots,
    float* __restrict__ outy1, float* __restrict__ outya, int R)
{
    long t = (long)blockIdx.x * 256 + threadIdx.x;
    int r = (int)(t >> 2);
    if (r >= R) return;
    int c = (int)(t & 3);
    int e   = __ldg(rowptr + r);
    int end = __ldg(rowptr + r + 1);
    float4 ay  = make_float4(0.f, 0.f, 0.f, 0.f);
    float4 axy = make_float4(0.f, 0.f, 0.f, 0.f);
    for (; e + 2 <= end; e += 2) {
        int s0 = __ldg(slots + e + 0);
        int s1 = __ldg(slots + e + 1);
        int n0 = __ldg(eid2nid + s0);
        int n1 = __ldg(eid2nid + s1);
        float4 vy0 = __ldg(F4(y) + (((size_t)s0 << 2) + c));
        float4 vy1 = __ldg(F4(y) + (((size_t)s1 << 2) + c));
        float4 vx0 = __ldg(F4(x) + (((size_t)n0 << 2) + c));
        float4 vx1 = __ldg(F4(x) + (((size_t)n1 << 2) + c));
        acc4(ay, vy0); acc4(ay, vy1);
        acc4(axy, vx0); acc4(axy, vx1);
    }
    for (; e < end; e++) {
        int s = __ldg(slots + e);
        int n = __ldg(eid2nid + s);
        acc4(ay,  __ldg(F4(y) + (((size_t)s << 2) + c)));
        acc4(axy, __ldg(F4(x) + (((size_t)n << 2) + c)));
    }
    reinterpret_cast<float4*>(outy1)[((size_t)r << 2) + c] = ay;
    reinterpret_cast<float4*>(outya)[((size_t)r << 2) + c] = axy;
}

// ---------------- combine + BN ---------------------------------------------

__global__ void __launch_bounds__(256) k_combine(
    const float* __restrict__ z0, const float* __restrict__ deg,
    const float* __restrict__ t2p, const float* __restrict__ t3p,
    const float* __restrict__ t4p, const float* __restrict__ t5p,
    const float* __restrict__ W, const float* __restrict__ B,
    float* __restrict__ out, double* __restrict__ stats, int n)
{
    __shared__ float4 sW[768];
    __shared__ float  sB[32];
    __shared__ float  sRed[32];
    int tid = threadIdx.x;
    const float4* W4 = reinterpret_cast<const float4*>(W);
    for (int i = tid; i < 768; i += 256) sW[i] = W4[i];
    if (tid < 32) {
        float b = 0.f;
        #pragma unroll
        for (int t = 0; t < 6; t++) b += B[t * 32 + tid];
        sB[tid] = b;
        sRed[tid] = 0.f;
    }
    __syncthreads();

    long r = (long)blockIdx.x * 256 + tid;
    if (r < (long)n) {
        float acc[32];
        #pragma unroll
        for (int j = 0; j < 32; j++) acc[j] = sB[j];
        float dg = __ldg(deg + r);
        #pragma unroll
        for (int t = 0; t < 6; t++) {
            const float* zp = (t <= 1) ? z0 : (t == 2 ? t2p : (t == 3 ? t3p : (t == 4 ? t4p : t5p)));
            const float4* z4p = F4(zp) + ((size_t)r << 2);
            float4 a0 = __ldg(z4p + 0);
            float4 a1 = __ldg(z4p + 1);
            float4 a2 = __ldg(z4p + 2);
            float4 a3 = __ldg(z4p + 3);
            if (t == 1) {
                a0.x *= dg; a0.y *= dg; a0.z *= dg; a0.w *= dg;
                a1.x *= dg; a1.y *= dg; a1.z *= dg; a1.w *= dg;
                a2.x *= dg; a2.y *= dg; a2.z *= dg; a2.w *= dg;
                a3.x *= dg; a3.y *= dg; a3.z *= dg; a3.w *= dg;
            }
            #pragma unroll
            for (int j = 0; j < 32; j++) {
                const float4* w = &sW[(t * 32 + j) * 4];
                float4 w0 = w[0], w1 = w[1], w2 = w[2], w3 = w[3];
                float s = acc[j];
                s += a0.x * w0.x + a0.y * w0.y + a0.z * w0.z + a0.w * w0.w;
                s += a1.x * w1.x + a1.y * w1.y + a1.z * w1.z + a1.w * w1.w;
                s += a2.x * w2.x + a2.y * w2.y + a2.z * w2.z + a2.w * w2.w;
                s += a3.x * w3.x + a3.y * w3.y + a3.z * w3.z + a3.w * w3.w;
                acc[j] = s;
            }
        }
        float h[16];
        #pragma unroll
        for (int j = 0; j < 16; j++) h[j] = acc[j] + fmaxf(acc[j + 16], 0.f);
        float4* o = reinterpret_cast<float4*>(out) + ((size_t)r << 2);
        o[0] = make_float4(h[0], h[1], h[2], h[3]);
        o[1] = make_float4(h[4], h[5], h[6], h[7]);
        o[2] = make_float4(h[8], h[9], h[10], h[11]);
        o[3] = make_float4(h[12], h[13], h[14], h[15]);
        #pragma unroll
        for (int c = 0; c < 16; c++) {
            atomicAdd(&sRed[c], h[c]);
            atomicAdd(&sRed[16 + c], h[c] * h[c]);
        }
    }
    __syncthreads();
    if (tid < 32) atomicAdd(&stats[tid], (double)sRed[tid]);
}

__global__ void k_bnprep(const double* __restrict__ stats, const float* __restrict__ w,
                         const float* __restrict__ b, float* __restrict__ coef, double n)
{
    int c = threadIdx.x;
    if (c >= 16) return;
    double m   = stats[c] / n;
    double var = stats[16 + c] / n - m * m;
    double s   = (double)w[c] / sqrt(var + (double)EPSV);
    coef[c]      = (float)s;
    coef[16 + c] = (float)((double)b[c] - m * s);
}

__global__ void __launch_bounds__(256) k_bn(
    float* __restrict__ h, const float* __restrict__ coef, long n4)
{
    long t = (long)blockIdx.x * 256 + threadIdx.x;
    if (t >= n4) return;
    int c = (int)(t & 3);
    float4 sc = reinterpret_cast<const float4*>(coef)[c];
    float4 sh = reinterpret_cast<const float4*>(coef)[4 + c];
    float4 v = reinterpret_cast<float4*>(h)[t];
    v.x = v.x * sc.x + sh.x;
    v.y = v.y * sc.y + sh.y;
    v.z = v.z * sc.z + sh.z;
    v.w = v.w * sc.w + sh.w;
    reinterpret_cast<float4*>(h)[t] = v;
}

// ---------------- host -----------------------------------------------------

static inline int cdiv(long a, int b) { return (int)((a + (long)b - 1) / b); }

extern "C" void kernel_launch(void* const* d_in, const int* in_sizes, int n_in,
                              void* d_out, int out_size)
{
    const float* x      = (const float*)d_in[0];
    const float* y      = (const float*)d_in[1];
    const float* deg_g  = (const float*)d_in[2];
    const float* deg_lg = (const float*)d_in[3];
    const float* thW    = (const float*)d_in[4];
    const float* thB    = (const float*)d_in[5];
    const float* gmW    = (const float*)d_in[6];
    const float* gmB    = (const float*)d_in[7];
    const float* bnxw   = (const float*)d_in[8];
    const float* bnxb   = (const float*)d_in[9];
    const float* bnyw   = (const float*)d_in[10];
    const float* bnyb   = (const float*)d_in[11];
    const int* src_g    = (const int*)d_in[12];
    const int* dst_g    = (const int*)d_in[13];
    const int* src_lg   = (const int*)d_in[14];
    const int* dst_lg   = (const int*)d_in[15];
    const int* eid      = (const int*)d_in[16];

    int N  = in_sizes[2];
    int E  = in_sizes[3];
    int EL = in_sizes[14];

    float *p_yx, *p_x1, *p_x2, *p_x4, *p_xt;
    float *p_ya, *p_y1, *p_y2, *p_y4, *p_t3, *p_coef;
    int *p_cnt_g, *p_rp_g, *p_bs_g, *p_cnt_lg, *p_rp_lg, *p_bs_lg, *p_slots_lg;
    int2* p_slots_g;
    double* p_stats;
    cudaGetSymbolAddress((void**)&p_yx, g_yx);
    cudaGetSymbolAddress((void**)&p_x1, g_x1);
    cudaGetSymbolAddress((void**)&p_x2, g_x2);
    cudaGetSymbolAddress((void**)&p_x4, g_x4);
    cudaGetSymbolAddress((void**)&p_xt, g_xt);
    cudaGetSymbolAddress((void**)&p_ya, g_ya);
    cudaGetSymbolAddress((void**)&p_y1, g_y1);
    cudaGetSymbolAddress((void**)&p_y2, g_y2);
    cudaGetSymbolAddress((void**)&p_y4, g_y4);
    cudaGetSymbolAddress((void**)&p_t3, g_t3);
    cudaGetSymbolAddress((void**)&p_cnt_g, g_cnt_g);
    cudaGetSymbolAddress((void**)&p_rp_g, g_rowptr_g);
    cudaGetSymbolAddress((void**)&p_bs_g, g_bsum_g);
    cudaGetSymbolAddress((void**)&p_slots_g, g_slots_g);
    cudaGetSymbolAddress((void**)&p_cnt_lg, g_cnt_lg);
    cudaGetSymbolAddress((void**)&p_rp_lg, g_rowptr_lg);
    cudaGetSymbolAddress((void**)&p_bs_lg, g_bsum_lg);
    cudaGetSymbolAddress((void**)&p_slots_lg, g_slots_lg);
    cudaGetSymbolAddress((void**)&p_stats, g_stats);
    cudaGetSymbolAddress((void**)&p_coef, g_coef);

    float* ox = (float*)d_out;
    float* oy = ox + (size_t)N * 16;

    const int TB = 256;
    int rp_g  = (N + 4095) & ~4095;
    int rp_lg = (E + 4095) & ~4095;
    int nb_g  = rp_g  / 4096;
    int nb_lg = rp_lg / 4096;

    cudaMemsetAsync(p_stats, 0, 64 * sizeof(double));

    // ---- build node-graph CSR (dst_g over E edges, N rows) ----
    cudaMemsetAsync(p_cnt_g, 0, (size_t)rp_g * 4);
    k_hist<<<cdiv(E, TB), TB>>>(dst_g, p_cnt_g, E);
    k_scan1<<<nb_g, TB>>>(p_cnt_g, p_bs_g);
    k_scan2<<<1, 1024>>>(p_bs_g, nb_g);
    k_scan3<<<nb_g, TB>>>(p_cnt_g, p_bs_g, p_rp_g, rp_g);
    cudaMemsetAsync(p_cnt_g, 0, (size_t)rp_g * 4);
    k_fill_g<<<cdiv(E, TB), TB>>>(src_g, dst_g, p_rp_g, p_cnt_g, p_slots_g, E);

    // ---- build line-graph CSR (dst_lg over EL edges, E rows) ----
    cudaMemsetAsync(p_cnt_lg, 0, (size_t)rp_lg * 4);
    k_hist<<<cdiv(EL, TB), TB>>>(dst_lg, p_cnt_lg, EL);
    k_scan1<<<nb_lg, TB>>>(p_cnt_lg, p_bs_lg);
    k_scan2<<<1, 1024>>>(p_bs_lg, nb_lg);
    k_scan3<<<nb_lg, TB>>>(p_cnt_lg, p_bs_lg, p_rp_lg, rp_lg);
    cudaMemsetAsync(p_cnt_lg, 0, (size_t)rp_lg * 4);
    k_fill_lg<<<cdiv(EL, TB), TB>>>(src_lg, dst_lg, p_rp_lg, p_cnt_lg, p_slots_lg, EL);

    // ---- node branch ----
    k_node_pass1<<<cdiv((long)N * 4, TB), TB>>>(x, y, p_rp_g, p_slots_g, p_x1, p_yx, N);
    k_spmm_csr2<<<cdiv((long)N * 4, TB), TB>>>(p_x1, p_rp_g, p_slots_g, p_x2, N);
    k_spmm_csr2<<<cdiv((long)N * 4, TB), TB>>>(p_x2, p_rp_g, p_slots_g, p_xt, N);
    k_spmm_csr2<<<cdiv((long)N * 4, TB), TB>>>(p_xt, p_rp_g, p_slots_g, p_x4, N);
    k_combine<<<cdiv(N, TB), TB>>>(x, deg_g, p_yx, p_x1, p_x2, p_x4, thW, thB, ox, p_stats, N);
    k_bnprep<<<1, 16>>>(p_stats, bnxw, bnxb, p_coef, (double)N);
    k_bn<<<cdiv((long)N * 4, TB), TB>>>(ox, p_coef, (long)N * 4);

    // ---- line (edge) branch ----
    k_line_pass1<<<cdiv((long)E * 4, TB), TB>>>(y, x, eid, p_rp_lg, p_slots_lg, p_y1, p_ya, E);
    k_spmm_csr<<<cdiv((long)E * 4, TB), TB>>>(p_y1, p_rp_lg, p_slots_lg, p_y2, E);
    k_spmm_csr<<<cdiv((long)E * 4, TB), TB>>>(p_y2, p_rp_lg, p_slots_lg, p_t3, E);
    k_spmm_csr<<<cdiv((long)E * 4, TB), TB>>>(p_t3, p_rp_lg, p_slots_lg, p_y4, E);
    k_combine<<<cdiv(E, TB), TB>>>(y, deg_lg, p_ya, p_y1, p_y2, p_y4, gmW, gmB, oy, p_stats + 32, E);
    k_bnprep<<<1, 16>>>(p_stats + 32, bnyw, bnyb, p_coef + 32, (double)E);
    k_bn<<<cdiv((long)E * 4, TB), TB>>>(oy, p_coef + 32, (long)E * 4);
}